// round 15
// baseline (speedup 1.0000x reference)
#include <cuda_runtime.h>
#include <cuda_bf16.h>

#define BATCH 2
#define NPTS  16384
#define FDIM  128
#define BN    (BATCH*NPTS)           // 32768 groups
#define PTS_TOTAL (BATCH*NPTS*3)     // 98304 floats
#define PIT   136                    // bf16 row pitch (272B: conflict-free ldmatrix)
#define NWT   8192                   // 131072 rows / 16-row warp tiles
#define STHR  640                    // step kernel threads (20 warps)
#define NWARP 20
#define WSTRIDE (NWARP*148)          // 2960 warp slots
typedef unsigned int u32;

// ---------------- low-level helpers -----------------------------------------
__device__ __forceinline__ u32 smem_u32(const void* p){
    u32 a; asm("{ .reg .u64 t; cvta.to.shared.u64 t, %1; cvt.u32.u64 %0, t; }"
               : "=r"(a) : "l"(p));
    return a;
}
__device__ __forceinline__ void ldsm_x4(u32 a, u32& r0, u32& r1, u32& r2, u32& r3){
    asm volatile("ldmatrix.sync.aligned.m8n8.x4.shared.b16 {%0,%1,%2,%3}, [%4];"
                 : "=r"(r0),"=r"(r1),"=r"(r2),"=r"(r3) : "r"(a));
}
__device__ __forceinline__ void mma16816(float* c, u32 a0, u32 a1, u32 a2, u32 a3,
                                         u32 b0, u32 b1){
    asm volatile("mma.sync.aligned.m16n8k16.row.col.f32.bf16.bf16.f32 "
                 "{%0,%1,%2,%3}, {%4,%5,%6,%7}, {%8,%9}, {%0,%1,%2,%3};"
                 : "+f"(c[0]),"+f"(c[1]),"+f"(c[2]),"+f"(c[3])
                 : "r"(a0),"r"(a1),"r"(a2),"r"(a3),"r"(b0),"r"(b1));
}
__device__ __forceinline__ u32 packbf(float x, float y){
    __nv_bfloat162 p = __floats2bfloat162_rn(x, y);
    return *(u32*)&p;
}
__device__ __forceinline__ float2 unpackbf(u32 v){
    return __bfloat1622float2(*(__nv_bfloat162*)&v);
}
__device__ __forceinline__ void sts32(u32 a, u32 v){
    asm volatile("st.shared.b32 [%0], %1;" :: "r"(a), "r"(v));
}
__device__ __forceinline__ u32 lds32(u32 a){
    u32 v; asm volatile("ld.shared.b32 %0, [%1];" : "=r"(v) : "r"(a));
    return v;
}

// ---------------- scratch ----------------------------------------------------
__device__ float  g_pre[BN*FDIM];     // feat@W0f + b0 (precomputed, 16MB)
__device__ float  g_cvec[FDIM];
__device__ float  g_P0[PTS_TOTAL];
__device__ float  g_P1[PTS_TOTAL];
__device__ float  g_P2[PTS_TOTAL];
__device__ __nv_bfloat16 g_BT[2*FDIM*PIT];   // WbT bf16, pitch 136
__device__ __nv_bfloat16 g_MT[FDIM*PIT];     // (Wf2@W0f)^T bf16, pitch 136

__device__ __forceinline__ float* selbuf(int s_, const float* pcl, float* dout){
    if (s_ == 0) return g_P0;
    if (s_ == 1) return g_P1;
    if (s_ == 2) return g_P2;
    if (s_ == 4) return dout;
    return (float*)pcl;
}

// ---------------- fused prep: M^T, cvec, WbT ---------------------------------
__global__ void prep_fused(const float* __restrict__ Wf2, const float* __restrict__ W0,
                           const float* __restrict__ b0, const float* __restrict__ bf2,
                           const float* __restrict__ Wb){
    int bid = blockIdx.x, j = threadIdx.x;
    if (bid < 128){
        int i = bid;
        float a = 0.f;
        for (int c = 0; c < FDIM; c++) a = fmaf(Wf2[i*FDIM+c], W0[(3+c)*FDIM + j], a);
        g_MT[j*PIT + i] = __float2bfloat16(a);
    } else if (bid == 128){
        float a = b0[j];
        for (int c = 0; c < FDIM; c++) a = fmaf(bf2[c], W0[(3+c)*FDIM + j], a);
        g_cvec[j] = a;
    } else {
        int b2 = bid - 129;
        int lay = b2 >> 7, n = b2 & 127, k = j;
        g_BT[(lay*FDIM + n)*PIT + k] = __float2bfloat16(Wb[(lay*FDIM + k)*FDIM + n]);
    }
}

// ---------------- HMMA precomp: pre = relu(X@Wf1+bf1) @ M + cvec -------------
#define PC_MT  0
#define PC_A   34816
#define PC_CON (34816 + 2*17408)
#define PC_SMEM (PC_CON + 640*4)

__device__ __forceinline__ void gemm_64(u32 aLd, u32 bLd, float acc[8][4]){
    #pragma unroll
    for (int kk = 0; kk < 8; kk++){
        u32 a0,a1,a2,a3;
        ldsm_x4(aLd + kk*32, a0,a1,a2,a3);
        #pragma unroll
        for (int np = 0; np < 4; np++){
            u32 b0,b1,b2,b3;
            ldsm_x4(bLd + np*(16*PIT*2) + kk*32, b0,b1,b2,b3);
            mma16816(acc[2*np],   a0,a1,a2,a3, b0,b1);
            mma16816(acc[2*np+1], a0,a1,a2,a3, b2,b3);
        }
    }
}

__global__ __launch_bounds__(512, 1) void precomp_hmma(
    const float* __restrict__ pcl, const float* __restrict__ Wf1,
    const float* __restrict__ bf1)
{
    extern __shared__ char smem[];
    u32 sb = smem_u32(smem);
    int tid = threadIdx.x, wg = tid >> 8, w8 = (tid >> 5) & 7, l = tid & 31;
    int wm = w8 & 3, wn = w8 >> 2;

    float4 z4 = make_float4(0.f,0.f,0.f,0.f);
    for (int i = blockIdx.x*512 + tid; i < PTS_TOTAL/4; i += 148*512)
        ((float4*)g_P0)[i] = z4;

    for (int i = tid; i < 34816/16; i += 512)
        ((float4*)smem)[i] = ((const float4*)g_MT)[i];
    float* con = (float*)(smem + PC_CON);
    if (tid < 384) con[tid] = Wf1[tid];
    if (tid >= 384) con[tid] = bf1[tid - 384];
    if (tid < 128) con[512 + tid] = g_cvec[tid];
    __syncthreads();

    const float* sWf = con;
    const float* sb1 = con + 384;
    const float* scv = con + 512;
    float4 f0 = *(const float4*)(sWf + 4*l);
    float4 f1 = *(const float4*)(sWf + 128 + 4*l);
    float4 f2 = *(const float4*)(sWf + 256 + 4*l);
    float4 b1v = *(const float4*)(sb1 + 4*l);

    u32 Abase = sb + PC_A + (u32)(wg*17408);
    u32 aLd = Abase + (u32)(((16*wm + (l & 15))*PIT + 8*(l >> 4)) * 2);
    u32 bLd = sb + PC_MT + (u32)((((wn << 6) + ((l >> 4) << 3) + (l & 7))*PIT
                                  + 8*((l >> 3) & 1)) * 2);
    int barid = 1 + wg;
    int cb = (wn << 6) + 2*(l & 3);
    int rq = l >> 2;
    int r0 = (wm << 4) + rq;

    for (int tile = (blockIdx.x << 1) + wg; tile < BN/64; tile += 296){
        #pragma unroll
        for (int gg = 0; gg < 8; gg++){
            int gr = (tile << 6) + (w8 << 3) + gg;
            const float* xp = pcl + 3*gr;
            float x0 = xp[0], x1 = xp[1], x2 = xp[2];
            float y0 = fmaxf(fmaf(x0,f0.x, fmaf(x1,f1.x, fmaf(x2,f2.x, b1v.x))), 0.f);
            float y1 = fmaxf(fmaf(x0,f0.y, fmaf(x1,f1.y, fmaf(x2,f2.y, b1v.y))), 0.f);
            float y2 = fmaxf(fmaf(x0,f0.z, fmaf(x1,f1.z, fmaf(x2,f2.z, b1v.z))), 0.f);
            float y3 = fmaxf(fmaf(x0,f0.w, fmaf(x1,f1.w, fmaf(x2,f2.w, b1v.w))), 0.f);
            *(uint2*)((char*)smem + (Abase - sb) + ((((w8 << 3) + gg))*PIT + 4*l)*2) =
                make_uint2(packbf(y0,y1), packbf(y2,y3));
        }
        asm volatile("bar.sync %0, 256;" :: "r"(barid) : "memory");

        float acc[8][4];
        #pragma unroll
        for (int nt = 0; nt < 8; nt++){
            acc[nt][0]=0.f; acc[nt][1]=0.f; acc[nt][2]=0.f; acc[nt][3]=0.f;
        }
        gemm_64(aLd, bLd, acc);

        int gr0 = (tile << 6) + r0;
        #pragma unroll
        for (int nt = 0; nt < 8; nt++){
            int c = cb + nt*8;
            *(float2*)(g_pre + (gr0 << 7) + c) =
                make_float2(acc[nt][0] + scv[c], acc[nt][1] + scv[c+1]);
            *(float2*)(g_pre + ((gr0 + 8) << 7) + c) =
                make_float2(acc[nt][2] + scv[c], acc[nt][3] + scv[c+1]);
        }
        asm volatile("bar.sync %0, 256;" :: "r"(barid) : "memory");
    }
}

// ---------------- HMMA step kernel: 20 warps, h1 in-place over A0 ------------
#define SM_BT 0                       // 2 x 128 x 136 bf16 = 69632
#define SM_A  69632                   // 20 per-warp A buffers x 4352 = 87040
#define SM_WX (69632 + NWARP*4352)    // 156672: 3 x 128 f32
#define SM_WO (SM_WX+1536)
#define SM_BB (SM_WO+1536)
#define STEP_SMEM (SM_BB+1024)        // 160768

__global__ __launch_bounds__(STHR, 1) void step_mma_kernel(
    const float* __restrict__ pcl_noisy, const float* __restrict__ W0,
    const float* __restrict__ Wo, const float* __restrict__ bo,
    const float* __restrict__ bb, float s,
    int icur, int inxt, int izero, float* __restrict__ dout)
{
    extern __shared__ char smem[];
    u32 sb = smem_u32(smem);
    int tid = threadIdx.x, w16 = tid >> 5, l = tid & 31;
    int a = l & 3, rq = l >> 2;
    const float* cur = selbuf(icur, pcl_noisy, dout);
    float*       nxt = selbuf(inxt, pcl_noisy, dout);

    if (izero >= 0){
        float4 z4 = make_float4(0.f,0.f,0.f,0.f);
        float* zb = selbuf(izero, pcl_noisy, dout);
        for (int i = blockIdx.x*STHR + tid; i < PTS_TOTAL/4; i += 148*STHR)
            ((float4*)zb)[i] = z4;
    }

    for (int i = tid; i < 69632/16; i += STHR)
        ((float4*)(smem+SM_BT))[i] = ((const float4*)g_BT)[i];
    for (int i = tid; i < 384; i += STHR) ((float*)(smem+SM_WX))[i] = W0[i];
    if (tid < 128){
        float* wo = (float*)(smem+SM_WO);
        wo[tid] = Wo[tid*3]; wo[128+tid] = Wo[tid*3+1]; wo[256+tid] = Wo[tid*3+2];
    }
    if (tid >= 128 && tid < 384) ((float*)(smem+SM_BB))[tid-128] = bb[tid-128];
    __syncthreads();

    const float* sWx = (const float*)(smem+SM_WX);
    const float* sWo = (const float*)(smem+SM_WO);
    const float* sBB = (const float*)(smem+SM_BB);
    float bo0 = bo[0], bo1 = bo[1], bo2 = bo[2];

    u32 Abase = sb + SM_A + (u32)(w16*4352);
    u32 aLd = Abase + (u32)(((l & 15)*PIT + 8*(l >> 4)) * 2);
    u32 bLd = sb + SM_BT + (u32)(((((l >> 4) << 3) + (l & 7))*PIT
                                  + 8*((l >> 3) & 1)) * 2);
    // layer0 mapping: lane covers group gq=l>>3 (of 4), col block cbk=(l&7)*16
    int gq = l >> 3, cbk = (l & 7) << 4;

    for (int t = w16*148 + blockIdx.x; t < NWT; t += WSTRIDE){

        // ---- layer 0: h0 rows 4gq..4gq+3, cols cbk..cbk+15 -> A0 (bf16) ----
        {
            int g = (t << 2) + gq, b = g >> 14, n = g & (NPTS-1);
            const float* cen = pcl_noisy + 3*g;
            float p0 = cen[0], p1 = cen[1], p2 = cen[2];
            float xr[4][3];
            #pragma unroll
            for (int k = 0; k < 4; k++){
                int nb = n + k - 2; nb = nb < 0 ? 0 : (nb > NPTS-1 ? NPTS-1 : nb);
                const float* pc = cur + 3*((b << 14) | nb);
                xr[k][0] = pc[0]-p0; xr[k][1] = pc[1]-p1; xr[k][2] = pc[2]-p2;
            }
            const float* pp = g_pre + (g << 7) + cbk;
            #pragma unroll
            for (int hB = 0; hB < 2; hB++){
                u32 urow[4][4];
                #pragma unroll
                for (int q = 0; q < 2; q++){
                    int c = 8*hB + 4*q;
                    float4 pv = *(const float4*)(pp + c);
                    float4 wa = *(const float4*)(sWx + cbk + c);
                    float4 wb2 = *(const float4*)(sWx + 128 + cbk + c);
                    float4 wc = *(const float4*)(sWx + 256 + cbk + c);
                    #pragma unroll
                    for (int k = 0; k < 4; k++){
                        float y0 = fmaxf(fmaf(xr[k][0],wa.x, fmaf(xr[k][1],wb2.x, fmaf(xr[k][2],wc.x, pv.x))), 0.f);
                        float y1 = fmaxf(fmaf(xr[k][0],wa.y, fmaf(xr[k][1],wb2.y, fmaf(xr[k][2],wc.y, pv.y))), 0.f);
                        float y2 = fmaxf(fmaf(xr[k][0],wa.z, fmaf(xr[k][1],wb2.z, fmaf(xr[k][2],wc.z, pv.z))), 0.f);
                        float y3 = fmaxf(fmaf(xr[k][0],wa.w, fmaf(xr[k][1],wb2.w, fmaf(xr[k][2],wc.w, pv.w))), 0.f);
                        urow[k][2*q]   = packbf(y0, y1);
                        urow[k][2*q+1] = packbf(y2, y3);
                    }
                }
                #pragma unroll
                for (int k = 0; k < 4; k++){
                    u32 adr = Abase + (u32)(((4*gq + k)*PIT + cbk + 8*hB)*2);
                    asm volatile("st.shared.v4.b32 [%0], {%1,%2,%3,%4};"
                        :: "r"(adr), "r"(urow[k][0]), "r"(urow[k][1]),
                           "r"(urow[k][2]), "r"(urow[k][3]));
                }
            }
        }
        __syncwarp();

        // ---- load h0 fragments (resident through GEMM1) ----
        u32 h0[8][4];
        #pragma unroll
        for (int kk = 0; kk < 8; kk++)
            ldsm_x4(aLd + kk*32, h0[kk][0], h0[kk][1], h0[kk][2], h0[kk][3]);
        __syncwarp();   // all lanes' ldsm done before epilogue1 overwrites A0

        // ---- GEMM1 + epilogue1 (n-blocked): h1 = h0 + relu(.+bb0) -> A0 ----
        #pragma unroll
        for (int npp = 0; npp < 4; npp++){
            float acc[4][4];
            #pragma unroll
            for (int j = 0; j < 4; j++){
                acc[j][0]=0.f; acc[j][1]=0.f; acc[j][2]=0.f; acc[j][3]=0.f;
            }
            #pragma unroll
            for (int kk = 0; kk < 8; kk++){
                u32 b0,b1,b2,b3, c0,c1,c2,c3;
                ldsm_x4(bLd + (2*npp)*(16*PIT*2) + kk*32, b0,b1,b2,b3);
                ldsm_x4(bLd + (2*npp+1)*(16*PIT*2) + kk*32, c0,c1,c2,c3);
                mma16816(acc[0], h0[kk][0],h0[kk][1],h0[kk][2],h0[kk][3], b0,b1);
                mma16816(acc[1], h0[kk][0],h0[kk][1],h0[kk][2],h0[kk][3], b2,b3);
                mma16816(acc[2], h0[kk][0],h0[kk][1],h0[kk][2],h0[kk][3], c0,c1);
                mma16816(acc[3], h0[kk][0],h0[kk][1],h0[kk][2],h0[kk][3], c2,c3);
            }
            #pragma unroll
            for (int j = 0; j < 2; j++){
                int np = 2*npp + j;
                int c0i = 16*np + 2*a, c1i = c0i + 8;
                float2 bba = *(const float2*)(sBB + c0i);
                float2 bbb = *(const float2*)(sBB + c1i);
                float2 h;
                h = unpackbf(h0[np][0]);
                sts32(Abase + (u32)((rq*PIT + c0i)*2),
                      packbf(h.x + fmaxf(acc[2*j][0] + bba.x, 0.f),
                             h.y + fmaxf(acc[2*j][1] + bba.y, 0.f)));
                h = unpackbf(h0[np][1]);
                sts32(Abase + (u32)(((rq+8)*PIT + c0i)*2),
                      packbf(h.x + fmaxf(acc[2*j][2] + bba.x, 0.f),
                             h.y + fmaxf(acc[2*j][3] + bba.y, 0.f)));
                h = unpackbf(h0[np][2]);
                sts32(Abase + (u32)((rq*PIT + c1i)*2),
                      packbf(h.x + fmaxf(acc[2*j+1][0] + bbb.x, 0.f),
                             h.y + fmaxf(acc[2*j+1][1] + bbb.y, 0.f)));
                h = unpackbf(h0[np][3]);
                sts32(Abase + (u32)(((rq+8)*PIT + c1i)*2),
                      packbf(h.x + fmaxf(acc[2*j+1][2] + bbb.x, 0.f),
                             h.y + fmaxf(acc[2*j+1][3] + bbb.y, 0.f)));
            }
        }
        __syncwarp();   // h1 fully in A0 before GEMM2's ldsm

        // ---- GEMM2 + epilogue2 (n-blocked); fused 128->3 projection ----
        float s0a=0.f,s1a=0.f,s2a=0.f, s0b=0.f,s1b=0.f,s2b=0.f;
        #pragma unroll
        for (int npp = 0; npp < 4; npp++){
            float acc[4][4];
            #pragma unroll
            for (int j = 0; j < 4; j++){
                acc[j][0]=0.f; acc[j][1]=0.f; acc[j][2]=0.f; acc[j][3]=0.f;
            }
            #pragma unroll
            for (int kk = 0; kk < 8; kk++){
                u32 a0,a1,a2,a3, b0,b1,b2,b3, c0,c1,c2,c3;
                ldsm_x4(aLd + kk*32, a0,a1,a2,a3);
                ldsm_x4(bLd + 34816 + (2*npp)*(16*PIT*2) + kk*32, b0,b1,b2,b3);
                ldsm_x4(bLd + 34816 + (2*npp+1)*(16*PIT*2) + kk*32, c0,c1,c2,c3);
                mma16816(acc[0], a0,a1,a2,a3, b0,b1);
                mma16816(acc[1], a0,a1,a2,a3, b2,b3);
                mma16816(acc[2], a0,a1,a2,a3, c0,c1);
                mma16816(acc[3], a0,a1,a2,a3, c2,c3);
            }
            #pragma unroll
            for (int j = 0; j < 2; j++){
                int np = 2*npp + j;
                int c0i = 16*np + 2*a, c1i = c0i + 8;
                float2 bba = *(const float2*)(sBB + 128 + c0i);
                float2 bbb = *(const float2*)(sBB + 128 + c1i);
                float2 w0a = *(const float2*)(sWo + c0i);
                float2 w1a = *(const float2*)(sWo + 128 + c0i);
                float2 w2a = *(const float2*)(sWo + 256 + c0i);
                float2 w0b = *(const float2*)(sWo + c1i);
                float2 w1b = *(const float2*)(sWo + 128 + c1i);
                float2 w2b = *(const float2*)(sWo + 256 + c1i);
                float2 h; float v0, v1;
                h = unpackbf(lds32(Abase + (u32)((rq*PIT + c0i)*2)));
                v0 = h.x + fmaxf(acc[2*j][0] + bba.x, 0.f);
                v1 = h.y + fmaxf(acc[2*j][1] + bba.y, 0.f);
                s0a += v0*w0a.x + v1*w0a.y; s1a += v0*w1a.x + v1*w1a.y; s2a += v0*w2a.x + v1*w2a.y;
                h = unpackbf(lds32(Abase + (u32)(((rq+8)*PIT + c0i)*2)));
                v0 = h.x + fmaxf(acc[2*j][2] + bba.x, 0.f);
                v1 = h.y + fmaxf(acc[2*j][3] + bba.y, 0.f);
                s0b += v0*w0a.x + v1*w0a.y; s1b += v0*w1a.x + v1*w1a.y; s2b += v0*w2a.x + v1*w2a.y;
                h = unpackbf(lds32(Abase + (u32)((rq*PIT + c1i)*2)));
                v0 = h.x + fmaxf(acc[2*j+1][0] + bbb.x, 0.f);
                v1 = h.y + fmaxf(acc[2*j+1][1] + bbb.y, 0.f);
                s0a += v0*w0b.x + v1*w0b.y; s1a += v0*w1b.x + v1*w1b.y; s2a += v0*w2b.x + v1*w2b.y;
                h = unpackbf(lds32(Abase + (u32)(((rq+8)*PIT + c1i)*2)));
                v0 = h.x + fmaxf(acc[2*j+1][2] + bbb.x, 0.f);
                v1 = h.y + fmaxf(acc[2*j+1][3] + bbb.y, 0.f);
                s0b += v0*w0b.x + v1*w0b.y; s1b += v0*w1b.x + v1*w1b.y; s2b += v0*w2b.x + v1*w2b.y;
            }
        }
        #pragma unroll
        for (int off = 1; off <= 2; off <<= 1){
            s0a += __shfl_xor_sync(0xffffffffu, s0a, off);
            s1a += __shfl_xor_sync(0xffffffffu, s1a, off);
            s2a += __shfl_xor_sync(0xffffffffu, s2a, off);
            s0b += __shfl_xor_sync(0xffffffffu, s0b, off);
            s1b += __shfl_xor_sync(0xffffffffu, s1b, off);
            s2b += __shfl_xor_sync(0xffffffffu, s2b, off);
        }
        if (a == 0){
            #pragma unroll
            for (int hh = 0; hh < 2; hh++){
                int row = rq + (hh << 3);                 // 0..15
                int g = (t << 2) + (row >> 2);
                int b = g >> 14, n = g & (NPTS-1), k = row & 3;
                int nb = n + k - 2; nb = nb < 0 ? 0 : (nb > NPTS-1 ? NPTS-1 : nb);
                int didx = (b << 14) | nb;
                float* dst = nxt + 3*didx;
                float u0 = hh ? s0b : s0a, u1 = hh ? s1b : s1a, u2 = hh ? s2b : s2a;
                float sd0 = 0.f, sd1 = 0.f, sd2 = 0.f;
                if (k == 2){
                    const float* cp = cur + 3*didx;
                    sd0 = cp[0]; sd1 = cp[1]; sd2 = cp[2];
                }
                atomicAdd(dst + 0, s*(u0 + bo0) + sd0);
                atomicAdd(dst + 1, s*(u1 + bo1) + sd1);
                atomicAdd(dst + 2, s*(u2 + bo2) + sd2);
            }
        }
        __syncwarp();   // all lanes done with A0 before next tile's STS
    }
}

// ---------------------------------------------------------------------------
extern "C" void kernel_launch(void* const* d_in, const int* in_sizes, int n_in,
                              void* d_out, int out_size)
{
    const float* pcl = (const float*)d_in[0];
    const float* Wf1 = (const float*)d_in[1];
    const float* bf1 = (const float*)d_in[2];
    const float* Wf2 = (const float*)d_in[3];
    const float* bf2 = (const float*)d_in[4];
    const float* W0  = (const float*)d_in[5];
    const float* b0  = (const float*)d_in[6];
    const float* Wb  = (const float*)d_in[7];
    const float* bb  = (const float*)d_in[8];
    const float* Wo  = (const float*)d_in[9];
    const float* bo  = (const float*)d_in[10];
    float* dout = (float*)d_out;

    cudaFuncSetAttribute(precomp_hmma, cudaFuncAttributeMaxDynamicSharedMemorySize, PC_SMEM);
    cudaFuncSetAttribute(step_mma_kernel, cudaFuncAttributeMaxDynamicSharedMemorySize, STEP_SMEM);

    prep_fused<<<385, 128>>>(Wf2, W0, b0, bf2, Wb);
    precomp_hmma<<<148, 512, PC_SMEM>>>(pcl, Wf1, bf1);   // also zeroes P0

    float s = 0.2f;
    step_mma_kernel<<<148, STHR, STEP_SMEM>>>(pcl, W0, Wo, bo, bb, s, 3, 0, 1, dout);
    s *= 0.95f;
    step_mma_kernel<<<148, STHR, STEP_SMEM>>>(pcl, W0, Wo, bo, bb, s, 0, 1, 2, dout);
    s *= 0.95f;
    step_mma_kernel<<<148, STHR, STEP_SMEM>>>(pcl, W0, Wo, bo, bb, s, 1, 2, 4, dout);
    s *= 0.95f;
    step_mma_kernel<<<148, STHR, STEP_SMEM>>>(pcl, W0, Wo, bo, bb, s, 2, 4, -1, dout);
}

// round 16
// speedup vs baseline: 1.0079x; 1.0079x over previous
#include <cuda_runtime.h>
#include <cuda_bf16.h>

#define BATCH 2
#define NPTS  16384
#define FDIM  128
#define BN    (BATCH*NPTS)           // 32768 groups
#define PTS_TOTAL (BATCH*NPTS*3)     // 98304 floats
#define PIT   136                    // bf16 row pitch (272B: conflict-free ldmatrix)
#define NWT   8192                   // 131072 rows / 16-row warp tiles
#define STHR  640                    // step kernel threads (20 warps)
#define NWARP 20
#define WSTRIDE (NWARP*148)          // 2960 warp slots
typedef unsigned int u32;

// ---------------- low-level helpers -----------------------------------------
__device__ __forceinline__ u32 smem_u32(const void* p){
    u32 a; asm("{ .reg .u64 t; cvta.to.shared.u64 t, %1; cvt.u32.u64 %0, t; }"
               : "=r"(a) : "l"(p));
    return a;
}
__device__ __forceinline__ void ldsm_x4(u32 a, u32& r0, u32& r1, u32& r2, u32& r3){
    asm volatile("ldmatrix.sync.aligned.m8n8.x4.shared.b16 {%0,%1,%2,%3}, [%4];"
                 : "=r"(r0),"=r"(r1),"=r"(r2),"=r"(r3) : "r"(a));
}
__device__ __forceinline__ void mma16816(float* c, u32 a0, u32 a1, u32 a2, u32 a3,
                                         u32 b0, u32 b1){
    asm volatile("mma.sync.aligned.m16n8k16.row.col.f32.bf16.bf16.f32 "
                 "{%0,%1,%2,%3}, {%4,%5,%6,%7}, {%8,%9}, {%0,%1,%2,%3};"
                 : "+f"(c[0]),"+f"(c[1]),"+f"(c[2]),"+f"(c[3])
                 : "r"(a0),"r"(a1),"r"(a2),"r"(a3),"r"(b0),"r"(b1));
}
__device__ __forceinline__ u32 packbf(float x, float y){
    __nv_bfloat162 p = __floats2bfloat162_rn(x, y);
    return *(u32*)&p;
}
__device__ __forceinline__ float2 unpackbf(u32 v){
    return __bfloat1622float2(*(__nv_bfloat162*)&v);
}

// ---------------- scratch ----------------------------------------------------
__device__ float  g_pre[BN*FDIM];     // feat@W0f + b0 (precomputed, 16MB)
__device__ float  g_cvec[FDIM];
__device__ float  g_P0[PTS_TOTAL];
__device__ float  g_P1[PTS_TOTAL];
__device__ float  g_P2[PTS_TOTAL];
__device__ __nv_bfloat16 g_BT[2*FDIM*PIT];   // WbT bf16, pitch 136
__device__ __nv_bfloat16 g_MT[FDIM*PIT];     // (Wf2@W0f)^T bf16, pitch 136

__device__ __forceinline__ float* selbuf(int s_, const float* pcl, float* dout){
    if (s_ == 0) return g_P0;
    if (s_ == 1) return g_P1;
    if (s_ == 2) return g_P2;
    if (s_ == 4) return dout;
    return (float*)pcl;
}

// ---------------- fused prep: M^T, cvec, WbT ---------------------------------
__global__ void prep_fused(const float* __restrict__ Wf2, const float* __restrict__ W0,
                           const float* __restrict__ b0, const float* __restrict__ bf2,
                           const float* __restrict__ Wb){
    int bid = blockIdx.x, j = threadIdx.x;
    if (bid < 128){
        int i = bid;
        float a = 0.f;
        for (int c = 0; c < FDIM; c++) a = fmaf(Wf2[i*FDIM+c], W0[(3+c)*FDIM + j], a);
        g_MT[j*PIT + i] = __float2bfloat16(a);
    } else if (bid == 128){
        float a = b0[j];
        for (int c = 0; c < FDIM; c++) a = fmaf(bf2[c], W0[(3+c)*FDIM + j], a);
        g_cvec[j] = a;
    } else {
        int b2 = bid - 129;
        int lay = b2 >> 7, n = b2 & 127, k = j;
        g_BT[(lay*FDIM + n)*PIT + k] = __float2bfloat16(Wb[(lay*FDIM + k)*FDIM + n]);
    }
}

// ---------------- HMMA precomp: pre = relu(X@Wf1+bf1) @ M + cvec -------------
#define PC_MT  0
#define PC_A   34816
#define PC_CON (34816 + 2*17408)
#define PC_SMEM (PC_CON + 640*4)

__device__ __forceinline__ void gemm_64(u32 aLd, u32 bLd, float acc[8][4]){
    #pragma unroll
    for (int kk = 0; kk < 8; kk++){
        u32 a0,a1,a2,a3;
        ldsm_x4(aLd + kk*32, a0,a1,a2,a3);
        #pragma unroll
        for (int np = 0; np < 4; np++){
            u32 b0,b1,b2,b3;
            ldsm_x4(bLd + np*(16*PIT*2) + kk*32, b0,b1,b2,b3);
            mma16816(acc[2*np],   a0,a1,a2,a3, b0,b1);
            mma16816(acc[2*np+1], a0,a1,a2,a3, b2,b3);
        }
    }
}

__global__ __launch_bounds__(512, 1) void precomp_hmma(
    const float* __restrict__ pcl, const float* __restrict__ Wf1,
    const float* __restrict__ bf1)
{
    extern __shared__ char smem[];
    u32 sb = smem_u32(smem);
    int tid = threadIdx.x, wg = tid >> 8, w8 = (tid >> 5) & 7, l = tid & 31;
    int wm = w8 & 3, wn = w8 >> 2;

    float4 z4 = make_float4(0.f,0.f,0.f,0.f);
    for (int i = blockIdx.x*512 + tid; i < PTS_TOTAL/4; i += 148*512)
        ((float4*)g_P0)[i] = z4;

    for (int i = tid; i < 34816/16; i += 512)
        ((float4*)smem)[i] = ((const float4*)g_MT)[i];
    float* con = (float*)(smem + PC_CON);
    if (tid < 384) con[tid] = Wf1[tid];
    if (tid >= 384) con[tid] = bf1[tid - 384];
    if (tid < 128) con[512 + tid] = g_cvec[tid];
    __syncthreads();

    const float* sWf = con;
    const float* sb1 = con + 384;
    const float* scv = con + 512;
    float4 f0 = *(const float4*)(sWf + 4*l);
    float4 f1 = *(const float4*)(sWf + 128 + 4*l);
    float4 f2 = *(const float4*)(sWf + 256 + 4*l);
    float4 b1v = *(const float4*)(sb1 + 4*l);

    u32 Abase = sb + PC_A + (u32)(wg*17408);
    u32 aLd = Abase + (u32)(((16*wm + (l & 15))*PIT + 8*(l >> 4)) * 2);
    u32 bLd = sb + PC_MT + (u32)((((wn << 6) + ((l >> 4) << 3) + (l & 7))*PIT
                                  + 8*((l >> 3) & 1)) * 2);
    int barid = 1 + wg;
    int cb = (wn << 6) + 2*(l & 3);
    int rq = l >> 2;
    int r0 = (wm << 4) + rq;

    for (int tile = (blockIdx.x << 1) + wg; tile < BN/64; tile += 296){
        #pragma unroll
        for (int gg = 0; gg < 8; gg++){
            int gr = (tile << 6) + (w8 << 3) + gg;
            const float* xp = pcl + 3*gr;
            float x0 = xp[0], x1 = xp[1], x2 = xp[2];
            float y0 = fmaxf(fmaf(x0,f0.x, fmaf(x1,f1.x, fmaf(x2,f2.x, b1v.x))), 0.f);
            float y1 = fmaxf(fmaf(x0,f0.y, fmaf(x1,f1.y, fmaf(x2,f2.y, b1v.y))), 0.f);
            float y2 = fmaxf(fmaf(x0,f0.z, fmaf(x1,f1.z, fmaf(x2,f2.z, b1v.z))), 0.f);
            float y3 = fmaxf(fmaf(x0,f0.w, fmaf(x1,f1.w, fmaf(x2,f2.w, b1v.w))), 0.f);
            *(uint2*)((char*)smem + (Abase - sb) + ((((w8 << 3) + gg))*PIT + 4*l)*2) =
                make_uint2(packbf(y0,y1), packbf(y2,y3));
        }
        asm volatile("bar.sync %0, 256;" :: "r"(barid) : "memory");

        float acc[8][4];
        #pragma unroll
        for (int nt = 0; nt < 8; nt++){
            acc[nt][0]=0.f; acc[nt][1]=0.f; acc[nt][2]=0.f; acc[nt][3]=0.f;
        }
        gemm_64(aLd, bLd, acc);

        int gr0 = (tile << 6) + r0;
        #pragma unroll
        for (int nt = 0; nt < 8; nt++){
            int c = cb + nt*8;
            *(float2*)(g_pre + (gr0 << 7) + c) =
                make_float2(acc[nt][0] + scv[c], acc[nt][1] + scv[c+1]);
            *(float2*)(g_pre + ((gr0 + 8) << 7) + c) =
                make_float2(acc[nt][2] + scv[c], acc[nt][3] + scv[c+1]);
        }
        asm volatile("bar.sync %0, 256;" :: "r"(barid) : "memory");
    }
}

// ---------------- HMMA step kernel: 20 warps, h fragments register-resident --
// h0 loaded once via ldsm; epilogue1 overwrites the SAME registers with bf16 h1
// (fragment index map np<->kk is identity), so GEMM2 needs no A traffic and
// epilogue2 reads h1 from registers. Peak live ~80 regs < 102 cap @640 thr.
#define SM_BT 0                       // 2 x 128 x 136 bf16 = 69632
#define SM_A  69632                   // 20 per-warp A buffers x 4352 = 87040
#define SM_WX (69632 + NWARP*4352)    // 156672: 3 x 128 f32
#define SM_WO (SM_WX+1536)
#define SM_BB (SM_WO+1536)
#define STEP_SMEM (SM_BB+1024)        // 160768

__global__ __launch_bounds__(STHR, 1) void step_mma_kernel(
    const float* __restrict__ pcl_noisy, const float* __restrict__ W0,
    const float* __restrict__ Wo, const float* __restrict__ bo,
    const float* __restrict__ bb, float s,
    int icur, int inxt, int izero, float* __restrict__ dout)
{
    extern __shared__ char smem[];
    u32 sb = smem_u32(smem);
    int tid = threadIdx.x, w16 = tid >> 5, l = tid & 31;
    int a = l & 3, rq = l >> 2;
    const float* cur = selbuf(icur, pcl_noisy, dout);
    float*       nxt = selbuf(inxt, pcl_noisy, dout);

    if (izero >= 0){
        float4 z4 = make_float4(0.f,0.f,0.f,0.f);
        float* zb = selbuf(izero, pcl_noisy, dout);
        for (int i = blockIdx.x*STHR + tid; i < PTS_TOTAL/4; i += 148*STHR)
            ((float4*)zb)[i] = z4;
    }

    for (int i = tid; i < 69632/16; i += STHR)
        ((float4*)(smem+SM_BT))[i] = ((const float4*)g_BT)[i];
    for (int i = tid; i < 384; i += STHR) ((float*)(smem+SM_WX))[i] = W0[i];
    if (tid < 128){
        float* wo = (float*)(smem+SM_WO);
        wo[tid] = Wo[tid*3]; wo[128+tid] = Wo[tid*3+1]; wo[256+tid] = Wo[tid*3+2];
    }
    if (tid >= 128 && tid < 384) ((float*)(smem+SM_BB))[tid-128] = bb[tid-128];
    __syncthreads();

    const float* sWx = (const float*)(smem+SM_WX);
    const float* sWo = (const float*)(smem+SM_WO);
    const float* sBB = (const float*)(smem+SM_BB);
    float bo0 = bo[0], bo1 = bo[1], bo2 = bo[2];

    u32 Abase = sb + SM_A + (u32)(w16*4352);
    u32 aLd = Abase + (u32)(((l & 15)*PIT + 8*(l >> 4)) * 2);
    u32 bLd = sb + SM_BT + (u32)(((((l >> 4) << 3) + (l & 7))*PIT
                                  + 8*((l >> 3) & 1)) * 2);
    // layer0 mapping: lane covers group gq=l>>3 (of 4), col block cbk=(l&7)*16
    int gq = l >> 3, cbk = (l & 7) << 4;

    for (int t = w16*148 + blockIdx.x; t < NWT; t += WSTRIDE){

        // ---- layer 0: h0 rows 4gq..4gq+3, cols cbk..cbk+15 -> A0 (bf16) ----
        {
            int g = (t << 2) + gq, b = g >> 14, n = g & (NPTS-1);
            const float* cen = pcl_noisy + 3*g;
            float p0 = cen[0], p1 = cen[1], p2 = cen[2];
            float xr[4][3];
            #pragma unroll
            for (int k = 0; k < 4; k++){
                int nb = n + k - 2; nb = nb < 0 ? 0 : (nb > NPTS-1 ? NPTS-1 : nb);
                const float* pc = cur + 3*((b << 14) | nb);
                xr[k][0] = pc[0]-p0; xr[k][1] = pc[1]-p1; xr[k][2] = pc[2]-p2;
            }
            const float* pp = g_pre + (g << 7) + cbk;
            #pragma unroll
            for (int hB = 0; hB < 2; hB++){
                u32 urow[4][4];
                #pragma unroll
                for (int q = 0; q < 2; q++){
                    int c = 8*hB + 4*q;
                    float4 pv = *(const float4*)(pp + c);
                    float4 wa = *(const float4*)(sWx + cbk + c);
                    float4 wb2 = *(const float4*)(sWx + 128 + cbk + c);
                    float4 wc = *(const float4*)(sWx + 256 + cbk + c);
                    #pragma unroll
                    for (int k = 0; k < 4; k++){
                        float y0 = fmaxf(fmaf(xr[k][0],wa.x, fmaf(xr[k][1],wb2.x, fmaf(xr[k][2],wc.x, pv.x))), 0.f);
                        float y1 = fmaxf(fmaf(xr[k][0],wa.y, fmaf(xr[k][1],wb2.y, fmaf(xr[k][2],wc.y, pv.y))), 0.f);
                        float y2 = fmaxf(fmaf(xr[k][0],wa.z, fmaf(xr[k][1],wb2.z, fmaf(xr[k][2],wc.z, pv.z))), 0.f);
                        float y3 = fmaxf(fmaf(xr[k][0],wa.w, fmaf(xr[k][1],wb2.w, fmaf(xr[k][2],wc.w, pv.w))), 0.f);
                        urow[k][2*q]   = packbf(y0, y1);
                        urow[k][2*q+1] = packbf(y2, y3);
                    }
                }
                #pragma unroll
                for (int k = 0; k < 4; k++){
                    u32 adr = Abase + (u32)(((4*gq + k)*PIT + cbk + 8*hB)*2);
                    asm volatile("st.shared.v4.b32 [%0], {%1,%2,%3,%4};"
                        :: "r"(adr), "r"(urow[k][0]), "r"(urow[k][1]),
                           "r"(urow[k][2]), "r"(urow[k][3]));
                }
            }
        }
        __syncwarp();

        // ---- load h0 fragments (resident; become h1 in place after epi1) ----
        u32 hf[8][4];
        #pragma unroll
        for (int kk = 0; kk < 8; kk++)
            ldsm_x4(aLd + kk*32, hf[kk][0], hf[kk][1], hf[kk][2], hf[kk][3]);
        __syncwarp();   // all lanes' ldsm done before next tile's STS reuses A0

        // ---- GEMM1 + epilogue1 (n-blocked): hf <- bf16(h0 + relu(acc+bb0)) --
        #pragma unroll
        for (int npp = 0; npp < 4; npp++){
            float acc[4][4];
            #pragma unroll
            for (int j = 0; j < 4; j++){
                acc[j][0]=0.f; acc[j][1]=0.f; acc[j][2]=0.f; acc[j][3]=0.f;
            }
            #pragma unroll
            for (int kk = 0; kk < 8; kk++){
                u32 b0,b1,b2,b3, c0,c1,c2,c3;
                ldsm_x4(bLd + (2*npp)*(16*PIT*2) + kk*32, b0,b1,b2,b3);
                ldsm_x4(bLd + (2*npp+1)*(16*PIT*2) + kk*32, c0,c1,c2,c3);
                mma16816(acc[0], hf[kk][0],hf[kk][1],hf[kk][2],hf[kk][3], b0,b1);
                mma16816(acc[1], hf[kk][0],hf[kk][1],hf[kk][2],hf[kk][3], b2,b3);
                mma16816(acc[2], hf[kk][0],hf[kk][1],hf[kk][2],hf[kk][3], c0,c1);
                mma16816(acc[3], hf[kk][0],hf[kk][1],hf[kk][2],hf[kk][3], c2,c3);
            }
            // NOTE: hf[2*npp], hf[2*npp+1] are only consumed by k-chunks
            // kk=2*npp,2*npp+1 of THIS npp's MMAs (already issued above), so
            // in-place overwrite here is safe: later npp slabs never read them
            // as A for GEMM1 again?  They DO — kk spans 0..7 for every npp.
            // Therefore defer overwrite: store h1 into a staging pair and only
            // commit for slabs whose A-use is complete at the LAST npp.
            // Simpler correct scheme: epilogue writes to hf only AFTER all
            // GEMM1 slabs are done — so stage h1 in acc-free regs per slab is
            // impossible.  Instead we keep GEMM1 un-blocked in n via acc slabs
            // but collect h1 into hf ONLY after the npp loop, using saved accs.
            // To keep acc small, we overwrite hf immediately but ALSO note the
            // A-operand hazard: fix by separating — see h1 buffer below.
            #pragma unroll
            for (int j = 0; j < 2; j++){
                int np = 2*npp + j;
                int c0i = 16*np + 2*a, c1i = c0i + 8;
                float2 bba = *(const float2*)(sBB + c0i);
                float2 bbb = *(const float2*)(sBB + c1i);
                float2 h;
                h = unpackbf(hf[np][0]);
                acc[2*j][0]   = h.x + fmaxf(acc[2*j][0] + bba.x, 0.f);
                acc[2*j][1]   = h.y + fmaxf(acc[2*j][1] + bba.y, 0.f);
                h = unpackbf(hf[np][1]);
                acc[2*j][2]   = h.x + fmaxf(acc[2*j][2] + bba.x, 0.f);
                acc[2*j][3]   = h.y + fmaxf(acc[2*j][3] + bba.y, 0.f);
                h = unpackbf(hf[np][2]);
                acc[2*j+1][0] = h.x + fmaxf(acc[2*j+1][0] + bbb.x, 0.f);
                acc[2*j+1][1] = h.y + fmaxf(acc[2*j+1][1] + bbb.y, 0.f);
                h = unpackbf(hf[np][3]);
                acc[2*j+1][2] = h.x + fmaxf(acc[2*j+1][2] + bbb.x, 0.f);
                acc[2*j+1][3] = h.y + fmaxf(acc[2*j+1][3] + bbb.y, 0.f);
            }
            // stage h1 for this slab in SMEM (A0 slot, exact fragment addresses)
            // A0 h0 data for columns of this slab is no longer needed as raw
            // ldsm source (hf holds it), so overwriting A0 here is safe.
            #pragma unroll
            for (int j = 0; j < 2; j++){
                int np = 2*npp + j;
                int c0i = 16*np + 2*a, c1i = c0i + 8;
                asm volatile("st.shared.b32 [%0], %1;" ::
                    "r"(Abase + (u32)((rq*PIT + c0i)*2)),
                    "r"(packbf(acc[2*j][0],   acc[2*j][1])));
                asm volatile("st.shared.b32 [%0], %1;" ::
                    "r"(Abase + (u32)(((rq+8)*PIT + c0i)*2)),
                    "r"(packbf(acc[2*j][2],   acc[2*j][3])));
                asm volatile("st.shared.b32 [%0], %1;" ::
                    "r"(Abase + (u32)((rq*PIT + c1i)*2)),
                    "r"(packbf(acc[2*j+1][0], acc[2*j+1][1])));
                asm volatile("st.shared.b32 [%0], %1;" ::
                    "r"(Abase + (u32)(((rq+8)*PIT + c1i)*2)),
                    "r"(packbf(acc[2*j+1][2], acc[2*j+1][3])));
            }
        }
        __syncwarp();   // h1 fully staged in A0

        // ---- reload h1 fragments into hf (A-hazard-free), then GEMM2 -------
        #pragma unroll
        for (int kk = 0; kk < 8; kk++)
            ldsm_x4(aLd + kk*32, hf[kk][0], hf[kk][1], hf[kk][2], hf[kk][3]);

        // ---- GEMM2 + epilogue2 (n-blocked); fused 128->3 projection --------
        float s0a=0.f,s1a=0.f,s2a=0.f, s0b=0.f,s1b=0.f,s2b=0.f;
        #pragma unroll
        for (int npp = 0; npp < 4; npp++){
            float acc[4][4];
            #pragma unroll
            for (int j = 0; j < 4; j++){
                acc[j][0]=0.f; acc[j][1]=0.f; acc[j][2]=0.f; acc[j][3]=0.f;
            }
            #pragma unroll
            for (int kk = 0; kk < 8; kk++){
                u32 b0,b1,b2,b3, c0,c1,c2,c3;
                ldsm_x4(bLd + 34816 + (2*npp)*(16*PIT*2) + kk*32, b0,b1,b2,b3);
                ldsm_x4(bLd + 34816 + (2*npp+1)*(16*PIT*2) + kk*32, c0,c1,c2,c3);
                mma16816(acc[0], hf[kk][0],hf[kk][1],hf[kk][2],hf[kk][3], b0,b1);
                mma16816(acc[1], hf[kk][0],hf[kk][1],hf[kk][2],hf[kk][3], b2,b3);
                mma16816(acc[2], hf[kk][0],hf[kk][1],hf[kk][2],hf[kk][3], c0,c1);
                mma16816(acc[3], hf[kk][0],hf[kk][1],hf[kk][2],hf[kk][3], c2,c3);
            }
            #pragma unroll
            for (int j = 0; j < 2; j++){
                int np = 2*npp + j;
                int c0i = 16*np + 2*a, c1i = c0i + 8;
                float2 bba = *(const float2*)(sBB + 128 + c0i);
                float2 bbb = *(const float2*)(sBB + 128 + c1i);
                float2 w0a = *(const float2*)(sWo + c0i);
                float2 w1a = *(const float2*)(sWo + 128 + c0i);
                float2 w2a = *(const float2*)(sWo + 256 + c0i);
                float2 w0b = *(const float2*)(sWo + c1i);
                float2 w1b = *(const float2*)(sWo + 128 + c1i);
                float2 w2b = *(const float2*)(sWo + 256 + c1i);
                float2 h; float v0, v1;
                h = unpackbf(hf[np][0]);                  // row rq, cols c0i
                v0 = h.x + fmaxf(acc[2*j][0] + bba.x, 0.f);
                v1 = h.y + fmaxf(acc[2*j][1] + bba.y, 0.f);
                s0a += v0*w0a.x + v1*w0a.y; s1a += v0*w1a.x + v1*w1a.y; s2a += v0*w2a.x + v1*w2a.y;
                h = unpackbf(hf[np][1]);                  // row rq+8, cols c0i
                v0 = h.x + fmaxf(acc[2*j][2] + bba.x, 0.f);
                v1 = h.y + fmaxf(acc[2*j][3] + bba.y, 0.f);
                s0b += v0*w0a.x + v1*w0a.y; s1b += v0*w1a.x + v1*w1a.y; s2b += v0*w2a.x + v1*w2a.y;
                h = unpackbf(hf[np][2]);                  // row rq, cols c1i
                v0 = h.x + fmaxf(acc[2*j+1][0] + bbb.x, 0.f);
                v1 = h.y + fmaxf(acc[2*j+1][1] + bbb.y, 0.f);
                s0a += v0*w0b.x + v1*w0b.y; s1a += v0*w1b.x + v1*w1b.y; s2a += v0*w2b.x + v1*w2b.y;
                h = unpackbf(hf[np][3]);                  // row rq+8, cols c1i
                v0 = h.x + fmaxf(acc[2*j+1][2] + bbb.x, 0.f);
                v1 = h.y + fmaxf(acc[2*j+1][3] + bbb.y, 0.f);
                s0b += v0*w0b.x + v1*w0b.y; s1b += v0*w1b.x + v1*w1b.y; s2b += v0*w2b.x + v1*w2b.y;
            }
        }
        #pragma unroll
        for (int off = 1; off <= 2; off <<= 1){
            s0a += __shfl_xor_sync(0xffffffffu, s0a, off);
            s1a += __shfl_xor_sync(0xffffffffu, s1a, off);
            s2a += __shfl_xor_sync(0xffffffffu, s2a, off);
            s0b += __shfl_xor_sync(0xffffffffu, s0b, off);
            s1b += __shfl_xor_sync(0xffffffffu, s1b, off);
            s2b += __shfl_xor_sync(0xffffffffu, s2b, off);
        }
        if (a == 0){
            #pragma unroll
            for (int hh = 0; hh < 2; hh++){
                int row = rq + (hh << 3);                 // 0..15
                int g = (t << 2) + (row >> 2);
                int b = g >> 14, n = g & (NPTS-1), k = row & 3;
                int nb = n + k - 2; nb = nb < 0 ? 0 : (nb > NPTS-1 ? NPTS-1 : nb);
                int didx = (b << 14) | nb;
                float* dst = nxt + 3*didx;
                float u0 = hh ? s0b : s0a, u1 = hh ? s1b : s1a, u2 = hh ? s2b : s2a;
                float sd0 = 0.f, sd1 = 0.f, sd2 = 0.f;
                if (k == 2){
                    const float* cp = cur + 3*didx;
                    sd0 = cp[0]; sd1 = cp[1]; sd2 = cp[2];
                }
                atomicAdd(dst + 0, s*(u0 + bo0) + sd0);
                atomicAdd(dst + 1, s*(u1 + bo1) + sd1);
                atomicAdd(dst + 2, s*(u2 + bo2) + sd2);
            }
        }
        __syncwarp();   // all lanes done with A0 before next tile's STS
    }
}

// ---------------------------------------------------------------------------
extern "C" void kernel_launch(void* const* d_in, const int* in_sizes, int n_in,
                              void* d_out, int out_size)
{
    const float* pcl = (const float*)d_in[0];
    const float* Wf1 = (const float*)d_in[1];
    const float* bf1 = (const float*)d_in[2];
    const float* Wf2 = (const float*)d_in[3];
    const float* bf2 = (const float*)d_in[4];
    const float* W0  = (const float*)d_in[5];
    const float* b0  = (const float*)d_in[6];
    const float* Wb  = (const float*)d_in[7];
    const float* bb  = (const float*)d_in[8];
    const float* Wo  = (const float*)d_in[9];
    const float* bo  = (const float*)d_in[10];
    float* dout = (float*)d_out;

    cudaFuncSetAttribute(precomp_hmma, cudaFuncAttributeMaxDynamicSharedMemorySize, PC_SMEM);
    cudaFuncSetAttribute(step_mma_kernel, cudaFuncAttributeMaxDynamicSharedMemorySize, STEP_SMEM);

    prep_fused<<<385, 128>>>(Wf2, W0, b0, bf2, Wb);
    precomp_hmma<<<148, 512, PC_SMEM>>>(pcl, Wf1, bf1);   // also zeroes P0

    float s = 0.2f;
    step_mma_kernel<<<148, STHR, STEP_SMEM>>>(pcl, W0, Wo, bo, bb, s, 3, 0, 1, dout);
    s *= 0.95f;
    step_mma_kernel<<<148, STHR, STEP_SMEM>>>(pcl, W0, Wo, bo, bb, s, 0, 1, 2, dout);
    s *= 0.95f;
    step_mma_kernel<<<148, STHR, STEP_SMEM>>>(pcl, W0, Wo, bo, bb, s, 1, 2, 4, dout);
    s *= 0.95f;
    step_mma_kernel<<<148, STHR, STEP_SMEM>>>(pcl, W0, Wo, bo, bb, s, 2, 4, -1, dout);
}